// round 16
// baseline (speedup 1.0000x reference)
#include <cuda_runtime.h>
#include <cuda_fp16.h>
#include <cstdint>

#define T_TOK 8192
#define HDIM  2048
#define IDIM  4096
#define NEXP  8
#define NSLOT (2 * T_TOK)

// ---------------- device scratch (static; no allocations allowed) -----------
__device__ int   g_cnt[NEXP];
__device__ int   g_tok[NEXP * T_TOK];
__device__ float g_wt [NEXP * T_TOK];
__device__ int   g_sl [2 * T_TOK];          // per token: (expert<<13)|pos, x2

__device__ __half g_x  [(size_t)T_TOK * HDIM];            // x fp16
__device__ __half g_w13[(size_t)NEXP * 2 * IDIM * HDIM];  // w13 fp16
__device__ __half g_w2 [(size_t)NEXP * HDIM * IDIM];      // w2  fp16
__device__ __half g_a  [(size_t)NSLOT * IDIM];            // act fp16
__device__ float  g_y  [(size_t)NSLOT * HDIM];            // per-slot weighted y

// ---------------- helpers ----------------------------------------------------
__device__ __forceinline__ uint32_t smem_u32(const void* p) {
    uint32_t a;
    asm("{ .reg .u64 t; cvta.to.shared.u64 t, %1; cvt.u32.u64 %0, t; }"
        : "=r"(a) : "l"(p));
    return a;
}
#define CP16(d, s) \
    asm volatile("cp.async.cg.shared.global [%0], [%1], 16;" :: "r"(d), "l"(s) : "memory")
#define CPC()  asm volatile("cp.async.commit_group;" ::: "memory")
#define CPW()  asm volatile("cp.async.wait_group 1;" ::: "memory")

#define LDSM4(r0, r1, r2, r3, addr) \
    asm volatile("ldmatrix.sync.aligned.m8n8.x4.shared.b16 {%0,%1,%2,%3}, [%4];" \
                 : "=r"(r0), "=r"(r1), "=r"(r2), "=r"(r3) : "r"(addr))

// fp32-accumulator MMA (settled best)
__device__ __forceinline__ void mma_h(float* c, const uint32_t* a,
                                      uint32_t b0, uint32_t b1) {
    asm volatile(
        "mma.sync.aligned.m16n8k16.row.col.f32.f16.f16.f32 "
        "{%0,%1,%2,%3}, {%4,%5,%6,%7}, {%8,%9}, {%0,%1,%2,%3};\n"
        : "+f"(c[0]), "+f"(c[1]), "+f"(c[2]), "+f"(c[3])
        : "r"(a[0]), "r"(a[1]), "r"(a[2]), "r"(a[3]), "r"(b0), "r"(b1));
}

__device__ __forceinline__ float silu(float x) { return x / (1.0f + __expf(-x)); }

__device__ __forceinline__ uint32_t h2u(__half2 h) {
    return *reinterpret_cast<uint32_t*>(&h);
}

__device__ __forceinline__ int exp_off(int e) {
    int s = 0;
#pragma unroll
    for (int i = 0; i < NEXP; i++) if (i < e) s += g_cnt[i];
    return s;
}

// ---------------- router (top-2, normalized weights) -------------------------
__global__ void k_router(const float* __restrict__ logits) {
    int t = blockIdx.x * blockDim.x + threadIdx.x;
    if (t >= T_TOK) return;
    float l[NEXP];
#pragma unroll
    for (int i = 0; i < NEXP; i++) l[i] = logits[t * NEXP + i];
    float best = -3.402823e38f, sec = -3.402823e38f;
    int bi = 0, si = 0;
#pragma unroll
    for (int i = 0; i < NEXP; i++) {
        float v = l[i];
        if (v > best) { sec = best; si = bi; best = v; bi = i; }
        else if (v > sec) { sec = v; si = i; }
    }
    float wa = 1.0f / (1.0f + expf(sec - best));
    float wb = 1.0f - wa;
    int p = atomicAdd(&g_cnt[bi], 1);
    g_tok[bi * T_TOK + p] = t;  g_wt[bi * T_TOK + p] = wa;
    g_sl[2 * t] = (bi << 13) | p;
    p = atomicAdd(&g_cnt[si], 1);
    g_tok[si * T_TOK + p] = t;  g_wt[si * T_TOK + p] = wb;
    g_sl[2 * t + 1] = (si << 13) | p;
}

// ---------------- prep: fp32 -> fp16, 4 independent float4 per iter ----------
__device__ __forceinline__ void round_store(const float* in, __half* hi, size_t n4) {
    size_t i = ((size_t)blockIdx.x * blockDim.x + threadIdx.x) * 4;
    const size_t stride = (size_t)gridDim.x * blockDim.x * 4;
    for (; i < n4; i += stride) {
        float4 v0 = reinterpret_cast<const float4*>(in)[i];
        float4 v1 = reinterpret_cast<const float4*>(in)[i + 1];
        float4 v2 = reinterpret_cast<const float4*>(in)[i + 2];
        float4 v3 = reinterpret_cast<const float4*>(in)[i + 3];
        uint4 u0, u1;
        u0.x = h2u(__halves2half2(__float2half_rn(v0.x), __float2half_rn(v0.y)));
        u0.y = h2u(__halves2half2(__float2half_rn(v0.z), __float2half_rn(v0.w)));
        u0.z = h2u(__halves2half2(__float2half_rn(v1.x), __float2half_rn(v1.y)));
        u0.w = h2u(__halves2half2(__float2half_rn(v1.z), __float2half_rn(v1.w)));
        u1.x = h2u(__halves2half2(__float2half_rn(v2.x), __float2half_rn(v2.y)));
        u1.y = h2u(__halves2half2(__float2half_rn(v2.z), __float2half_rn(v2.w)));
        u1.z = h2u(__halves2half2(__float2half_rn(v3.x), __float2half_rn(v3.y)));
        u1.w = h2u(__halves2half2(__float2half_rn(v3.z), __float2half_rn(v3.w)));
        *reinterpret_cast<uint4*>(hi + i * 4)     = u0;
        *reinterpret_cast<uint4*>(hi + i * 4 + 8) = u1;
    }
}
__global__ void k_prep_x(const float* __restrict__ in) {
    if (blockIdx.x == 0 && threadIdx.x < NEXP) g_cnt[threadIdx.x] = 0;
    round_store(in, g_x, (size_t)T_TOK * HDIM / 4);
}
__global__ void k_prep_w13(const float* __restrict__ in) {
    round_store(in, g_w13, (size_t)NEXP * 2 * IDIM * HDIM / 4);
}
__global__ void k_prep_w2(const float* __restrict__ in) {
    round_store(in, g_w2, (size_t)NEXP * HDIM * IDIM / 4);
}

// ---------------- GEMM config ------------------------------------------------
// block 128M x 128N(smem rows), 8 warps (2M x 4N), warp tile 64x32
// KC=64 halves, 2-stage cp.async pipeline, smem 74KB -> 3 CTAs/SM (24 warps)
#define KC     64
#define SROWB  144                      // 64 halves (128B) + 16B pad
#define BOFF   (128 * SROWB)            // B rows start after 128 A rows
#define STG_   (256 * SROWB)            // 36864B per stage
#define NSTG   2
#define SM_TOK 0
#define SM_WT  1024
#define SM_BUF 2048
#define SMEM_SZ (SM_BUF + NSTG * STG_)  // 75776B -> 3 CTAs/SM (227.3KB)

// stage issue: A 2 thr/row x 64B; B 2 thr/row x 64B
#define G_ISSUE(c, s) do {                                            \
        uint32_t so = (s) * STG_;                                     \
        const __half* pa = asrc + (c) * KC;                           \
        CP16(adst + so,      pa);      CP16(adst + so + 16, pa + 8);  \
        CP16(adst + so + 32, pa + 16); CP16(adst + so + 48, pa + 24); \
        const __half* pb = bsrc + (c) * KC;                           \
        CP16(bdst + so,      pb);      CP16(bdst + so + 16, pb + 8);  \
        CP16(bdst + so + 32, pb + 16); CP16(bdst + so + 48, pb + 24); \
    } while (0)

// per-chunk: 4 ks-steps x (6 LDSM + 16 MMA)
#define CHUNK_MMAS(so) do {                                           \
    _Pragma("unroll")                                                 \
    for (int ks = 0; ks < 4; ks++) {                                  \
        uint32_t af[4][4], bf[2][4];                                  \
        _Pragma("unroll")                                             \
        for (int mf = 0; mf < 4; mf++)                                \
            LDSM4(af[mf][0], af[mf][1], af[mf][2], af[mf][3],         \
                  aA[mf] + (so) + ks * 32);                           \
        _Pragma("unroll")                                             \
        for (int p = 0; p < 2; p++)                                   \
            LDSM4(bf[p][0], bf[p][1], bf[p][2], bf[p][3],             \
                  aB[p] + (so) + ks * 32);                            \
        _Pragma("unroll")                                             \
        for (int p = 0; p < 2; p++) {                                 \
            _Pragma("unroll")                                         \
            for (int mf = 0; mf < 4; mf++) {                          \
                mma_h(acc[mf][2 * p],     af[mf], bf[p][0], bf[p][2]);\
                mma_h(acc[mf][2 * p + 1], af[mf], bf[p][1], bf[p][3]);\
            }                                                         \
        }                                                             \
    }                                                                 \
} while (0)

// ---------------- gemm1: act = silu(x W13g^T) * (x W13u^T) -------------------
// grid (T/128, IDIM/64, E), 256 threads, 3 CTAs/SM
__global__ __launch_bounds__(256, 3) void k_gemm1(const int dummy) {
    extern __shared__ char dsm[];
    const int e = blockIdx.z;
    const int cnt = g_cnt[e];
    const int m0 = blockIdx.x * 128;
    if (m0 >= cnt) return;
    const int off_e = exp_off(e);
    const int n0 = blockIdx.y * 64;
    const int tid = threadIdx.x, wid = tid >> 5, lane = tid & 31;
    int* sTok = (int*)(dsm + SM_TOK);
    if (tid < 128) {
        int r = m0 + tid; if (r >= cnt) r = cnt - 1;
        sTok[tid] = g_tok[e * T_TOK + r];
    }
    __syncthreads();
    const uint32_t sb = smem_u32(dsm);

    const int arow = tid >> 1, ahalf = tid & 1;
    const __half* asrc = g_x + (size_t)sTok[arow] * HDIM + ahalf * 32;
    const uint32_t adst = sb + SM_BUF + arow * SROWB + ahalf * 64;
    const int brow = tid >> 1, bq = tid & 1;
    const int bwn = brow >> 5, bidx = brow & 31;
    const int wrow = (bidx < 16) ? (n0 + bwn * 16 + bidx)
                                 : (IDIM + n0 + bwn * 16 + (bidx - 16));
    const __half* bsrc = g_w13 + ((size_t)e * 2 * IDIM + wrow) * HDIM + bq * 32;
    const uint32_t bdst = sb + SM_BUF + BOFF + brow * SROWB + bq * 64;

    const int wm = wid & 1, wn = wid >> 1, g = lane >> 2, tg = lane & 3;
    const int lrow = lane & 15, lcq = (lane >> 4) * 16;
    uint32_t aA[4], aB[2];
#pragma unroll
    for (int mf = 0; mf < 4; mf++)
        aA[mf] = sb + SM_BUF + (wm * 64 + mf * 16 + lrow) * SROWB + lcq;
#pragma unroll
    for (int p = 0; p < 2; p++)
        aB[p] = sb + SM_BUF + BOFF + (wn * 32 + p * 16 + lrow) * SROWB + lcq;

    float acc[4][4][4];
#pragma unroll
    for (int a = 0; a < 4; a++)
#pragma unroll
        for (int b = 0; b < 4; b++)
#pragma unroll
            for (int c = 0; c < 4; c++) acc[a][b][c] = 0.f;

    G_ISSUE(0, 0); CPC();
    G_ISSUE(1, 1); CPC();

    const int NCH = HDIM / KC;   // 32
    for (int c = 0; c < NCH; c++) {
        CPW();
        __syncthreads();
        const uint32_t so = (c & 1) * STG_;
        CHUNK_MMAS(so);
        __syncthreads();               // NSTG=2: protect slot reuse across warps
        if (c + 2 < NCH) G_ISSUE(c + 2, (c + 2) & 1);
        CPC();
    }

    // epilogue: silu(gate)*up -> act fp16  (nf 0,1 = gate; nf 2,3 = up)
#pragma unroll
    for (int mf = 0; mf < 4; mf++) {
#pragma unroll
        for (int nf = 0; nf < 2; nf++) {
            int col = n0 + wn * 16 + nf * 8 + tg * 2;
#pragma unroll
            for (int h = 0; h < 2; h++) {
                int rl = wm * 64 + mf * 16 + g + h * 8;
                int r = m0 + rl;
                if (r < cnt) {
                    float a0 = silu(acc[mf][nf][2 * h])     * acc[mf][nf + 2][2 * h];
                    float a1 = silu(acc[mf][nf][2 * h + 1]) * acc[mf][nf + 2][2 * h + 1];
                    size_t o = (size_t)(off_e + r) * IDIM + col;
                    *reinterpret_cast<__half2*>(g_a + o) =
                        __halves2half2(__float2half_rn(a0), __float2half_rn(a1));
                }
            }
        }
    }
    (void)dummy;
}

// ---------------- gemm2: y[slot] = w * (act W2^T) ----------------------------
// grid (T/128, HDIM/128, E), 256 threads, 3 CTAs/SM
__global__ __launch_bounds__(256, 3) void k_gemm2(const int dummy) {
    extern __shared__ char dsm[];
    const int e = blockIdx.z;
    const int cnt = g_cnt[e];
    const int m0 = blockIdx.x * 128;
    if (m0 >= cnt) return;
    const int off_e = exp_off(e);
    const int n0 = blockIdx.y * 128;
    const int tid = threadIdx.x, wid = tid >> 5, lane = tid & 31;
    float* sW = (float*)(dsm + SM_WT);
    if (tid < 128) {
        int r = m0 + tid; if (r >= cnt) r = cnt - 1;
        sW[tid] = g_wt[e * T_TOK + r];
    }
    __syncthreads();
    const uint32_t sb = smem_u32(dsm);

    const int arow = tid >> 1, ahalf = tid & 1;
    int rr = m0 + arow; if (rr >= cnt) rr = cnt - 1;
    const __half* asrc = g_a + (size_t)(off_e + rr) * IDIM + ahalf * 32;
    const uint32_t adst = sb + SM_BUF + arow * SROWB + ahalf * 64;
    const int brow = tid >> 1, bq = tid & 1;
    const __half* bsrc = g_w2 + ((size_t)e * HDIM + (n0 + brow)) * IDIM + bq * 32;
    const uint32_t bdst = sb + SM_BUF + BOFF + brow * SROWB + bq * 64;

    const int wm = wid & 1, wn = wid >> 1, g = lane >> 2, tg = lane & 3;
    const int lrow = lane & 15, lcq = (lane >> 4) * 16;
    uint32_t aA[4], aB[2];
#pragma unroll
    for (int mf = 0; mf < 4; mf++)
        aA[mf] = sb + SM_BUF + (wm * 64 + mf * 16 + lrow) * SROWB + lcq;
#pragma unroll
    for (int p = 0; p < 2; p++)
        aB[p] = sb + SM_BUF + BOFF + (wn * 32 + p * 16 + lrow) * SROWB + lcq;

    float acc[4][4][4];
#pragma unroll
    for (int a = 0; a < 4; a++)
#pragma unroll
        for (int b = 0; b < 4; b++)
#pragma unroll
            for (int c = 0; c < 4; c++) acc[a][b][c] = 0.f;

    G_ISSUE(0, 0); CPC();
    G_ISSUE(1, 1); CPC();

    const int NCH = IDIM / KC;   // 64
    for (int c = 0; c < NCH; c++) {
        CPW();
        __syncthreads();
        const uint32_t so = (c & 1) * STG_;
        CHUNK_MMAS(so);
        __syncthreads();               // NSTG=2: protect slot reuse across warps
        if (c + 2 < NCH) G_ISSUE(c + 2, (c + 2) & 1);
        CPC();
    }

    // epilogue: weighted store to per-slot y buffer (no atomics)
#pragma unroll
    for (int mf = 0; mf < 4; mf++) {
#pragma unroll
        for (int nf = 0; nf < 4; nf++) {
            int col = n0 + wn * 32 + nf * 8 + tg * 2;
#pragma unroll
            for (int h = 0; h < 2; h++) {
                int rl = wm * 64 + mf * 16 + g + h * 8;
                int r = m0 + rl;
                if (r < cnt) {
                    float w = sW[rl];
                    size_t o = (size_t)(off_e + r) * HDIM + col;
                    *reinterpret_cast<float2*>(g_y + o) =
                        make_float2(acc[mf][nf][2 * h] * w, acc[mf][nf][2 * h + 1] * w);
                }
            }
        }
    }
    (void)dummy;
}

// ---------------- combine: out[t] = y[slot0] + y[slot1] ----------------------
__global__ void k_combine(float* __restrict__ out) {
    int off[NEXP];
    {
        int s = 0;
#pragma unroll
        for (int i = 0; i < NEXP; i++) { off[i] = s; s += g_cnt[i]; }
    }
    const size_t n4 = (size_t)T_TOK * HDIM / 4;
    size_t i = (size_t)blockIdx.x * blockDim.x + threadIdx.x;
    for (; i < n4; i += (size_t)gridDim.x * blockDim.x) {
        int t = (int)(i / (HDIM / 4));
        int c = (int)(i % (HDIM / 4));
        int p0 = g_sl[2 * t], p1 = g_sl[2 * t + 1];
        size_t s0 = (size_t)off[p0 >> 13] + (p0 & 8191);
        size_t s1 = (size_t)off[p1 >> 13] + (p1 & 8191);
        float4 a = reinterpret_cast<const float4*>(g_y)[s0 * (HDIM / 4) + c];
        float4 b = reinterpret_cast<const float4*>(g_y)[s1 * (HDIM / 4) + c];
        reinterpret_cast<float4*>(out)[i] =
            make_float4(a.x + b.x, a.y + b.y, a.z + b.z, a.w + b.w);
    }
}

// ---------------- launch ------------------------------------------------------
// Order keeps GEMM1 in ncu's capture slot (#4):
//   1 prep_x (also zeroes g_cnt), 2 prep_w13, 3 router, 4 GEMM1,
//   5 prep_w2, 6 GEMM2, 7 combine
extern "C" void kernel_launch(void* const* d_in, const int* in_sizes, int n_in,
                              void* d_out, int out_size) {
    const float* x      = (const float*)d_in[0];   // [T, H]
    const float* logits = (const float*)d_in[1];   // [T, E]
    const float* w13    = (const float*)d_in[2];   // [E, 2I, H]
    const float* w2     = (const float*)d_in[3];   // [E, H, I]
    float* out = (float*)d_out;                    // [T, H]
    (void)in_sizes; (void)n_in; (void)out_size;

    cudaFuncSetAttribute(k_gemm1, cudaFuncAttributeMaxDynamicSharedMemorySize, SMEM_SZ);
    cudaFuncSetAttribute(k_gemm2, cudaFuncAttributeMaxDynamicSharedMemorySize, SMEM_SZ);

    k_prep_x  <<<2048, 256>>>(x);
    k_prep_w13<<<8192, 256>>>(w13);
    k_router<<<T_TOK / 256, 256>>>(logits);

    dim3 g1(T_TOK / 128, IDIM / 64, NEXP);
    k_gemm1<<<g1, 256, SMEM_SZ>>>(0);

    k_prep_w2 <<<4096, 256>>>(w2);

    dim3 g2(T_TOK / 128, HDIM / 128, NEXP);
    k_gemm2<<<g2, 256, SMEM_SZ>>>(0);

    k_combine<<<2048, 256>>>(out);
}

// round 17
// speedup vs baseline: 1.4763x; 1.4763x over previous
#include <cuda_runtime.h>
#include <cuda_fp16.h>
#include <cstdint>

#define T_TOK 8192
#define HDIM  2048
#define IDIM  4096
#define NEXP  8
#define NSLOT (2 * T_TOK)

// ---------------- device scratch (static; no allocations allowed) -----------
__device__ int   g_cnt[NEXP];
__device__ int   g_tok[NEXP * T_TOK];
__device__ float g_wt [NEXP * T_TOK];

__device__ __half g_x  [(size_t)T_TOK * HDIM];            // x fp16
__device__ __half g_w13[(size_t)NEXP * 2 * IDIM * HDIM];  // w13 fp16
__device__ __half g_w2 [(size_t)NEXP * HDIM * IDIM];      // w2  fp16
__device__ __half g_a  [(size_t)NSLOT * IDIM];            // act fp16

// ---------------- helpers ----------------------------------------------------
__device__ __forceinline__ uint32_t smem_u32(const void* p) {
    uint32_t a;
    asm("{ .reg .u64 t; cvta.to.shared.u64 t, %1; cvt.u32.u64 %0, t; }"
        : "=r"(a) : "l"(p));
    return a;
}
#define CP16(d, s) \
    asm volatile("cp.async.cg.shared.global [%0], [%1], 16;" :: "r"(d), "l"(s) : "memory")
#define CPC()  asm volatile("cp.async.commit_group;" ::: "memory")
#define CPW()  asm volatile("cp.async.wait_group 2;" ::: "memory")

#define LDSM4(r0, r1, r2, r3, addr) \
    asm volatile("ldmatrix.sync.aligned.m8n8.x4.shared.b16 {%0,%1,%2,%3}, [%4];" \
                 : "=r"(r0), "=r"(r1), "=r"(r2), "=r"(r3) : "r"(addr))

// fp32-accumulator MMA (settled best)
__device__ __forceinline__ void mma_h(float* c, const uint32_t* a,
                                      uint32_t b0, uint32_t b1) {
    asm volatile(
        "mma.sync.aligned.m16n8k16.row.col.f32.f16.f16.f32 "
        "{%0,%1,%2,%3}, {%4,%5,%6,%7}, {%8,%9}, {%0,%1,%2,%3};\n"
        : "+f"(c[0]), "+f"(c[1]), "+f"(c[2]), "+f"(c[3])
        : "r"(a[0]), "r"(a[1]), "r"(a[2]), "r"(a[3]), "r"(b0), "r"(b1));
}

__device__ __forceinline__ float silu(float x) { return x / (1.0f + __expf(-x)); }

__device__ __forceinline__ uint32_t h2u(__half2 h) {
    return *reinterpret_cast<uint32_t*>(&h);
}

__device__ __forceinline__ int exp_off(int e) {
    int s = 0;
#pragma unroll
    for (int i = 0; i < NEXP; i++) if (i < e) s += g_cnt[i];
    return s;
}

// ---------------- router (top-2, normalized weights) -------------------------
__global__ void k_router(const float* __restrict__ logits) {
    int t = blockIdx.x * blockDim.x + threadIdx.x;
    if (t >= T_TOK) return;
    float l[NEXP];
#pragma unroll
    for (int i = 0; i < NEXP; i++) l[i] = logits[t * NEXP + i];
    float best = -3.402823e38f, sec = -3.402823e38f;
    int bi = 0, si = 0;
#pragma unroll
    for (int i = 0; i < NEXP; i++) {
        float v = l[i];
        if (v > best) { sec = best; si = bi; best = v; bi = i; }
        else if (v > sec) { sec = v; si = i; }
    }
    float wa = 1.0f / (1.0f + expf(sec - best));
    float wb = 1.0f - wa;
    int p = atomicAdd(&g_cnt[bi], 1);
    g_tok[bi * T_TOK + p] = t;  g_wt[bi * T_TOK + p] = wa;
    p = atomicAdd(&g_cnt[si], 1);
    g_tok[si * T_TOK + p] = t;  g_wt[si * T_TOK + p] = wb;
}

// ---------------- prep: fp32 -> fp16, 2 independent float4 per iter ----------
__device__ __forceinline__ void round_store(const float* in, __half* hi, size_t n4) {
    size_t i = ((size_t)blockIdx.x * blockDim.x + threadIdx.x) * 2;
    const size_t stride = (size_t)gridDim.x * blockDim.x * 2;
    for (; i < n4; i += stride) {
        float4 v0 = reinterpret_cast<const float4*>(in)[i];
        float4 v1 = reinterpret_cast<const float4*>(in)[i + 1];
        uint4 u;
        u.x = h2u(__halves2half2(__float2half_rn(v0.x), __float2half_rn(v0.y)));
        u.y = h2u(__halves2half2(__float2half_rn(v0.z), __float2half_rn(v0.w)));
        u.z = h2u(__halves2half2(__float2half_rn(v1.x), __float2half_rn(v1.y)));
        u.w = h2u(__halves2half2(__float2half_rn(v1.z), __float2half_rn(v1.w)));
        *reinterpret_cast<uint4*>(hi + i * 4) = u;
    }
}
__global__ void k_prep_x(const float* __restrict__ in, float* __restrict__ out) {
    if (blockIdx.x == 0 && threadIdx.x < NEXP) g_cnt[threadIdx.x] = 0;
    // zero the output (gemm2 accumulates into it atomically)
    const size_t no4 = (size_t)T_TOK * HDIM / 4;
    float4 z = make_float4(0.f, 0.f, 0.f, 0.f);
    for (size_t j = (size_t)blockIdx.x * blockDim.x + threadIdx.x; j < no4;
         j += (size_t)gridDim.x * blockDim.x)
        reinterpret_cast<float4*>(out)[j] = z;
    round_store(in, g_x, (size_t)T_TOK * HDIM / 4);
}
__global__ void k_prep_w13(const float* __restrict__ in) {
    round_store(in, g_w13, (size_t)NEXP * 2 * IDIM * HDIM / 4);
}
__global__ void k_prep_w2(const float* __restrict__ in) {
    round_store(in, g_w2, (size_t)NEXP * HDIM * IDIM / 4);
}

// ---------------- GEMM config (R9 banked-best core) ---------------------------
// block 256M x 128N, 16 warps (4M x 4N), warp tile 64x32
// KC=64 halves per chunk, 4-stage cp.async pipeline (2-deep prefetch), 1 CTA/SM
#define KC     64
#define SROWB  144                      // 64 halves (128B) + 16B pad
#define BOFF   (256 * SROWB)            // B rows start after 256 A rows
#define STG_   (384 * SROWB)            // 55296B per stage
#define NSTG   4
#define SM_TOK 0
#define SM_WT  1024
#define SM_BUF 2048
#define SMEM_SZ (SM_BUF + NSTG * STG_)  // 223232B

// ---------------- gemm1: act = silu(x W13g^T) * (x W13u^T) -------------------
// grid (T/256, IDIM/64, E), 512 threads
__global__ __launch_bounds__(512) void k_gemm1(const int dummy) {
    extern __shared__ char dsm[];
    const int e = blockIdx.z;
    const int cnt = g_cnt[e];
    const int m0 = blockIdx.x * 256;
    if (m0 >= cnt) return;
    const int off_e = exp_off(e);
    const int n0 = blockIdx.y * 64;
    const int tid = threadIdx.x, wid = tid >> 5, lane = tid & 31;
    int* sTok = (int*)(dsm + SM_TOK);
    if (tid < 256) {
        int r = m0 + tid; if (r >= cnt) r = cnt - 1;
        sTok[tid] = g_tok[e * T_TOK + r];
    }
    __syncthreads();
    const uint32_t sb = smem_u32(dsm);

    // staging: A 256 rows, 2 thr/row x 64B; B 128 rows, 4 thr/row x 32B
    const int arow = tid >> 1, ahalf = tid & 1;
    const __half* asrc = g_x + (size_t)sTok[arow] * HDIM + ahalf * 32;
    const uint32_t adst = sb + SM_BUF + arow * SROWB + ahalf * 64;
    const int brow = tid >> 2, bq = tid & 3;
    const int bwn = brow >> 5, bidx = brow & 31;
    const int wrow = (bidx < 16) ? (n0 + bwn * 16 + bidx)
                                 : (IDIM + n0 + bwn * 16 + (bidx - 16));
    const __half* bsrc = g_w13 + ((size_t)e * 2 * IDIM + wrow) * HDIM + bq * 16;
    const uint32_t bdst = sb + SM_BUF + BOFF + brow * SROWB + bq * 32;

    const int wm = wid & 3, wn = wid >> 2, g = lane >> 2, tg = lane & 3;
    const int lrow = lane & 15, lcq = (lane >> 4) * 16;
    uint32_t aA[4], aB[2];
#pragma unroll
    for (int mf = 0; mf < 4; mf++)
        aA[mf] = sb + SM_BUF + (wm * 64 + mf * 16 + lrow) * SROWB + lcq;
#pragma unroll
    for (int p = 0; p < 2; p++)
        aB[p] = sb + SM_BUF + BOFF + (wn * 32 + p * 16 + lrow) * SROWB + lcq;

    float acc[4][4][4];
#pragma unroll
    for (int a = 0; a < 4; a++)
#pragma unroll
        for (int b = 0; b < 4; b++)
#pragma unroll
            for (int c = 0; c < 4; c++) acc[a][b][c] = 0.f;

#define G1_ISSUE(c, s) do {                                           \
        uint32_t so = (s) * STG_;                                     \
        const __half* pa = asrc + (c) * KC;                           \
        CP16(adst + so,      pa);      CP16(adst + so + 16, pa + 8);  \
        CP16(adst + so + 32, pa + 16); CP16(adst + so + 48, pa + 24); \
        const __half* pb = bsrc + (c) * KC;                           \
        CP16(bdst + so, pb);           CP16(bdst + so + 16, pb + 8);  \
    } while (0)

    G1_ISSUE(0, 0); CPC();
    G1_ISSUE(1, 1); CPC();
    G1_ISSUE(2, 2); CPC();

    const int NCH = HDIM / KC;   // 32
    for (int c = 0; c < NCH; c++) {
        CPW();
        __syncthreads();
        const uint32_t so = (c % NSTG) * STG_;
#pragma unroll
        for (int ks = 0; ks < 4; ks++) {
            uint32_t af[4][4];
#pragma unroll
            for (int mf = 0; mf < 4; mf++)
                LDSM4(af[mf][0], af[mf][1], af[mf][2], af[mf][3],
                      aA[mf] + so + ks * 32);
#pragma unroll
            for (int p = 0; p < 2; p++) {
                uint32_t b00, b01, b10, b11;
                LDSM4(b00, b01, b10, b11, aB[p] + so + ks * 32);
#pragma unroll
                for (int mf = 0; mf < 4; mf++) {
                    mma_h(acc[mf][2 * p],     af[mf], b00, b10);
                    mma_h(acc[mf][2 * p + 1], af[mf], b01, b11);
                }
            }
        }
        if (c + 3 < NCH) G1_ISSUE(c + 3, (c + 3) % NSTG);
        CPC();
    }
#undef G1_ISSUE

    // epilogue: silu(gate)*up -> act fp16  (nf 0,1 = gate; nf 2,3 = up)
#pragma unroll
    for (int mf = 0; mf < 4; mf++) {
#pragma unroll
        for (int nf = 0; nf < 2; nf++) {
            int col = n0 + wn * 16 + nf * 8 + tg * 2;
#pragma unroll
            for (int h = 0; h < 2; h++) {
                int rl = wm * 64 + mf * 16 + g + h * 8;
                int r = m0 + rl;
                if (r < cnt) {
                    float a0 = silu(acc[mf][nf][2 * h])     * acc[mf][nf + 2][2 * h];
                    float a1 = silu(acc[mf][nf][2 * h + 1]) * acc[mf][nf + 2][2 * h + 1];
                    size_t o = (size_t)(off_e + r) * IDIM + col;
                    *reinterpret_cast<__half2*>(g_a + o) =
                        __halves2half2(__float2half_rn(a0), __float2half_rn(a1));
                }
            }
        }
    }
    (void)dummy;
}

// ---------------- gemm2: out[tok] += w * (act W2^T)  (atomic combine) --------
// grid (T/256, HDIM/128, E), 512 threads
__global__ __launch_bounds__(512) void k_gemm2(float* __restrict__ out) {
    extern __shared__ char dsm[];
    const int e = blockIdx.z;
    const int cnt = g_cnt[e];
    const int m0 = blockIdx.x * 256;
    if (m0 >= cnt) return;
    const int off_e = exp_off(e);
    const int n0 = blockIdx.y * 128;
    const int tid = threadIdx.x, wid = tid >> 5, lane = tid & 31;
    int*   sTok = (int*)(dsm + SM_TOK);
    float* sW   = (float*)(dsm + SM_WT);
    if (tid < 256) {
        int r = m0 + tid; if (r >= cnt) r = cnt - 1;
        sTok[tid] = g_tok[e * T_TOK + r];
        sW[tid]   = g_wt [e * T_TOK + r];
    }
    __syncthreads();
    const uint32_t sb = smem_u32(dsm);

    const int arow = tid >> 1, ahalf = tid & 1;
    int rr = m0 + arow; if (rr >= cnt) rr = cnt - 1;
    const __half* asrc = g_a + (size_t)(off_e + rr) * IDIM + ahalf * 32;
    const uint32_t adst = sb + SM_BUF + arow * SROWB + ahalf * 64;
    const int brow = tid >> 2, bq = tid & 3;
    const __half* bsrc = g_w2 + ((size_t)e * HDIM + (n0 + brow)) * IDIM + bq * 16;
    const uint32_t bdst = sb + SM_BUF + BOFF + brow * SROWB + bq * 32;

    const int wm = wid & 3, wn = wid >> 2, g = lane >> 2, tg = lane & 3;
    const int lrow = lane & 15, lcq = (lane >> 4) * 16;
    uint32_t aA[4], aB[2];
#pragma unroll
    for (int mf = 0; mf < 4; mf++)
        aA[mf] = sb + SM_BUF + (wm * 64 + mf * 16 + lrow) * SROWB + lcq;
#pragma unroll
    for (int p = 0; p < 2; p++)
        aB[p] = sb + SM_BUF + BOFF + (wn * 32 + p * 16 + lrow) * SROWB + lcq;

    float acc[4][4][4];
#pragma unroll
    for (int a = 0; a < 4; a++)
#pragma unroll
        for (int b = 0; b < 4; b++)
#pragma unroll
            for (int c = 0; c < 4; c++) acc[a][b][c] = 0.f;

#define G2_ISSUE(c, s) do {                                           \
        uint32_t so = (s) * STG_;                                     \
        const __half* pa = asrc + (c) * KC;                           \
        CP16(adst + so,      pa);      CP16(adst + so + 16, pa + 8);  \
        CP16(adst + so + 32, pa + 16); CP16(adst + so + 48, pa + 24); \
        const __half* pb = bsrc + (c) * KC;                           \
        CP16(bdst + so, pb);           CP16(bdst + so + 16, pb + 8);  \
    } while (0)

    G2_ISSUE(0, 0); CPC();
    G2_ISSUE(1, 1); CPC();
    G2_ISSUE(2, 2); CPC();

    const int NCH = IDIM / KC;   // 64
    for (int c = 0; c < NCH; c++) {
        CPW();
        __syncthreads();
        const uint32_t so = (c % NSTG) * STG_;
#pragma unroll
        for (int ks = 0; ks < 4; ks++) {
            uint32_t af[4][4];
#pragma unroll
            for (int mf = 0; mf < 4; mf++)
                LDSM4(af[mf][0], af[mf][1], af[mf][2], af[mf][3],
                      aA[mf] + so + ks * 32);
#pragma unroll
            for (int p = 0; p < 2; p++) {
                uint32_t b00, b01, b10, b11;
                LDSM4(b00, b01, b10, b11, aB[p] + so + ks * 32);
#pragma unroll
                for (int mf = 0; mf < 4; mf++) {
                    mma_h(acc[mf][2 * p],     af[mf], b00, b10);
                    mma_h(acc[mf][2 * p + 1], af[mf], b01, b11);
                }
            }
        }
        if (c + 3 < NCH) G2_ISSUE(c + 3, (c + 3) % NSTG);
        CPC();
    }
#undef G2_ISSUE

    // epilogue: weighted atomic accumulate directly into out (no combine pass)
#pragma unroll
    for (int mf = 0; mf < 4; mf++) {
#pragma unroll
        for (int nf = 0; nf < 4; nf++) {
            int col = n0 + wn * 32 + nf * 8 + tg * 2;
#pragma unroll
            for (int h = 0; h < 2; h++) {
                int rl = wm * 64 + mf * 16 + g + h * 8;
                int r = m0 + rl;
                if (r < cnt) {
                    float w = sW[rl];
                    float* op = out + (size_t)sTok[rl] * HDIM + col;
                    atomicAdd(op,     acc[mf][nf][2 * h] * w);
                    atomicAdd(op + 1, acc[mf][nf][2 * h + 1] * w);
                }
            }
        }
    }
}

// ---------------- launch ------------------------------------------------------
// Order keeps GEMM1 in ncu's capture slot (#4):
//   1 prep_x (zeroes g_cnt + out), 2 prep_w13, 3 router, 4 GEMM1,
//   5 prep_w2, 6 GEMM2
extern "C" void kernel_launch(void* const* d_in, const int* in_sizes, int n_in,
                              void* d_out, int out_size) {
    const float* x      = (const float*)d_in[0];   // [T, H]
    const float* logits = (const float*)d_in[1];   // [T, E]
    const float* w13    = (const float*)d_in[2];   // [E, 2I, H]
    const float* w2     = (const float*)d_in[3];   // [E, H, I]
    float* out = (float*)d_out;                    // [T, H]
    (void)in_sizes; (void)n_in; (void)out_size;

    cudaFuncSetAttribute(k_gemm1, cudaFuncAttributeMaxDynamicSharedMemorySize, SMEM_SZ);
    cudaFuncSetAttribute(k_gemm2, cudaFuncAttributeMaxDynamicSharedMemorySize, SMEM_SZ);

    k_prep_x  <<<2048, 256>>>(x, out);
    k_prep_w13<<<8192, 256>>>(w13);
    k_router<<<T_TOK / 256, 256>>>(logits);

    dim3 g1(T_TOK / 256, IDIM / 64, NEXP);
    k_gemm1<<<g1, 512, SMEM_SZ>>>(0);

    k_prep_w2 <<<4096, 256>>>(w2);

    dim3 g2(T_TOK / 256, HDIM / 128, NEXP);
    k_gemm2<<<g2, 512, SMEM_SZ>>>(out);
}